// round 13
// baseline (speedup 1.0000x reference)
#include <cuda_runtime.h>
#include <cuda_bf16.h>
#include <cuda_fp16.h>
#include <math.h>
#include <stdint.h>

// Problem constants
#define NPTS 8192
#define DIM  512
#define KNN  15
#define KEEP 24     // approx candidates kept per row (margin for bf16+fp16 error)
#define NPAIR 105   // 15*14/2
#define FULLM 0xFFFFFFFFu

// ---------------- scratch (device globals: no allocation allowed) -------------
__device__ __align__(16) __half g_sqd[(size_t)NPTS * NPTS];      // 128 MB approx sq dists
__device__ float  g_norms[NPTS];
__device__ __align__(16) __nv_bfloat16 g_H[(size_t)NPTS * DIM];  // bf16 embeddings
__device__ int    g_knni[NPTS * KNN];
__device__ float  g_knnd[NPTS * 16];               // exact knn sq-dists (sorted)
__device__ double g_acc[2];                        // [0]=curv sumsq, [1]=ang sumsq

// ================= PTX helpers (generic sm_80+ only; NO tcgen05) =================
__device__ __forceinline__ uint32_t smem_u32(const void* p) {
    uint32_t a;
    asm("{ .reg .u64 t; cvta.to.shared.u64 t, %1; cvt.u32.u64 %0, t; }" : "=r"(a) : "l"(p));
    return a;
}
__device__ __forceinline__ void cp_async16(uint32_t dst, const void* src) {
    asm volatile("cp.async.cg.shared.global [%0], [%1], 16;" :: "r"(dst), "l"(src));
}
#define CP_COMMIT() asm volatile("cp.async.commit_group;" ::: "memory")

__device__ __forceinline__ void ldmat4(uint32_t* r, uint32_t saddr) {
    asm volatile("ldmatrix.sync.aligned.m8n8.x4.shared.b16 {%0,%1,%2,%3}, [%4];"
                 : "=r"(r[0]), "=r"(r[1]), "=r"(r[2]), "=r"(r[3]) : "r"(saddr));
}
__device__ __forceinline__ void mma_bf16(float* d, const uint32_t* a,
                                         uint32_t b0, uint32_t b1) {
    asm volatile(
        "mma.sync.aligned.m16n8k16.row.col.f32.bf16.bf16.f32 "
        "{%0,%1,%2,%3}, {%4,%5,%6,%7}, {%8,%9}, {%0,%1,%2,%3};"
        : "+f"(d[0]), "+f"(d[1]), "+f"(d[2]), "+f"(d[3])
        : "r"(a[0]), "r"(a[1]), "r"(a[2]), "r"(a[3]), "r"(b0), "r"(b1));
}

// ================= kernel 0: zero accumulators =================
__global__ void zero_acc_kernel() {
    g_acc[0] = 0.0; g_acc[1] = 0.0;
}

// ================= kernel 1: norms (fp32) + bf16 convert, one read of E ========
__global__ void prep_kernel(const float* __restrict__ E) {
    int row  = blockIdx.x * 8 + (threadIdx.x >> 5);
    int lane = threadIdx.x & 31;
    const float4* r = (const float4*)(E + (size_t)row * DIM);
    __nv_bfloat162* H2 = (__nv_bfloat162*)(g_H + (size_t)row * DIM);
    float s = 0.f;
    #pragma unroll
    for (int c4 = lane; c4 < DIM / 4; c4 += 32) {
        float4 v = r[c4];
        s = fmaf(v.x, v.x, fmaf(v.y, v.y, fmaf(v.z, v.z, fmaf(v.w, v.w, s))));
        H2[c4 * 2]     = __floats2bfloat162_rn(v.x, v.y);
        H2[c4 * 2 + 1] = __floats2bfloat162_rn(v.z, v.w);
    }
    #pragma unroll
    for (int o = 16; o; o >>= 1) s += __shfl_xor_sync(FULLM, s, o);
    if (!lane) g_norms[row] = s;
}

// ================= kernel 2: bf16 mma.sync Gram -> approx sq dists (fp16) =======
// CTA tile 128x256, BK=32, 8 warps @ 64x64, fp32 accum. Triangular 2c<=r grid.
#define SROW 80                 // 64B data + 16B pad per K-slab row
#define STAGEB (384 * SROW)     // A(128 rows) + B(256 rows) = 30720 B
#define MIRS 136                // S transpose stride (halves)
#define SMEM_GEMM (256 * MIRS * 2 > 2 * STAGEB ? 256 * MIRS * 2 : 2 * STAGEB)  // 69632

__global__ void __launch_bounds__(256, 1) gemm_bf16_kernel() {
    extern __shared__ __align__(128) char sbuf[];
    const uint32_t sb = smem_u32(sbuf);
    const int tid  = threadIdx.x;
    const int lane = tid & 31;
    const int wid  = tid >> 5;

    // triangular decode at (r:128-row, c:256-col) granularity: 2c <= r
    int t = blockIdx.x;
    int r = 2 * (int)sqrtf((float)t);
    if (r > 63) r = 63;
    #pragma unroll 1
    while (r < 63) {
        int rn = r + 1, m = rn >> 1;
        int cm = (rn & 1) ? (m + 1) * (m + 1) : m * m + m;
        if (cm <= t) r = rn; else break;
    }
    #pragma unroll 1
    for (;;) {
        int m = r >> 1;
        int cm = (r & 1) ? (m + 1) * (m + 1) : m * m + m;
        if (cm > t) r--; else break;
    }
    int m0 = r >> 1;
    int cumr = (r & 1) ? (m0 + 1) * (m0 + 1) : m0 * m0 + m0;
    int c = t - cumr;

    const int row0 = r * 128, col0 = c * 256;
    const int wm = (wid >> 2) * 64;
    const int wn = (wid & 3) * 64;
    const int hw = wn >> 7;

    const bool low0 = (col0 + 128) <= row0;
    const bool low1 = (col0 + 256) <= row0;
    const bool upH  = hw ? (col0 + 128 > row0) : false;
    const bool lowH = hw ? low1 : low0;

    float d[4][8][4];
    #pragma unroll
    for (int mt = 0; mt < 4; mt++)
        #pragma unroll
        for (int nt = 0; nt < 8; nt++)
            #pragma unroll
            for (int q = 0; q < 4; q++) d[mt][nt][q] = 0.f;

    {
        uint32_t s0 = sb;
        #pragma unroll
        for (int i = 0; i < 6; i++) {
            int q = tid + i * 256;
            int rw = q >> 2, cc = q & 3;
            const __nv_bfloat16* src = (rw < 128)
                ? &g_H[(size_t)(row0 + rw) * DIM + cc * 8]
                : &g_H[(size_t)(col0 + rw - 128) * DIM + cc * 8];
            cp_async16(s0 + rw * SROW + cc * 16, src);
        }
        CP_COMMIT();
    }

    for (int st = 0; st < 16; st++) {
        if (st < 15) {
            int kk = (st + 1) * 32;
            uint32_t s1 = sb + ((st + 1) & 1) * STAGEB;
            #pragma unroll
            for (int i = 0; i < 6; i++) {
                int q = tid + i * 256;
                int rw = q >> 2, cc = q & 3;
                const __nv_bfloat16* src = (rw < 128)
                    ? &g_H[(size_t)(row0 + rw) * DIM + kk + cc * 8]
                    : &g_H[(size_t)(col0 + rw - 128) * DIM + kk + cc * 8];
                cp_async16(s1 + rw * SROW + cc * 16, src);
            }
            CP_COMMIT();
            asm volatile("cp.async.wait_group 1;" ::: "memory");
        } else {
            asm volatile("cp.async.wait_group 0;" ::: "memory");
        }
        __syncthreads();

        uint32_t aT = sb + (st & 1) * STAGEB;
        uint32_t bT = aT + 128 * SROW;
        #pragma unroll
        for (int ks = 0; ks < 2; ks++) {
            int kb = ks * 32;
            uint32_t aF[4][4], bF[4][4];
            #pragma unroll
            for (int mt = 0; mt < 4; mt++)
                ldmat4(aF[mt], aT + (wm + mt * 16 + (lane & 15)) * SROW + kb + (lane >> 4) * 16);
            #pragma unroll
            for (int g = 0; g < 4; g++)
                ldmat4(bF[g], bT + (wn + g * 16 + (lane & 15)) * SROW + kb + (lane >> 4) * 16);
            #pragma unroll
            for (int mt = 0; mt < 4; mt++)
                #pragma unroll
                for (int nt = 0; nt < 8; nt++)
                    mma_bf16(d[mt][nt], aF[mt], bF[nt >> 1][nt & 1], bF[nt >> 1][(nt & 1) + 2]);
        }
        __syncthreads();
    }

    // ---------------- epilogue ----------------
    const float INF = __int_as_float(0x7f800000);
    __half* S = (__half*)sbuf;

    #pragma unroll
    for (int mt = 0; mt < 4; mt++) {
        int i0 = row0 + wm + mt * 16 + (lane >> 2);
        int i1 = i0 + 8;
        float n0 = g_norms[i0], n1 = g_norms[i1];
        #pragma unroll
        for (int nt = 0; nt < 8; nt++) {
            int jl = wn + nt * 8 + (lane & 3) * 2;
            int j0 = col0 + jl;
            float ja = g_norms[j0], jb = g_norms[j0 + 1];
            float o00 = fmaxf(n0 + ja - 2.f * d[mt][nt][0], 0.f);
            float o01 = fmaxf(n0 + jb - 2.f * d[mt][nt][1], 0.f);
            float o10 = fmaxf(n1 + ja - 2.f * d[mt][nt][2], 0.f);
            float o11 = fmaxf(n1 + jb - 2.f * d[mt][nt][3], 0.f);
            if (i0 == j0)     o00 = INF;
            if (i0 == j0 + 1) o01 = INF;
            if (i1 == j0)     o10 = INF;
            if (i1 == j0 + 1) o11 = INF;
            if (!upH) {
                *(__half2*)&g_sqd[(size_t)i0 * NPTS + j0] = __floats2half2_rn(o00, o01);
                *(__half2*)&g_sqd[(size_t)i1 * NPTS + j0] = __floats2half2_rn(o10, o11);
            }
            if (lowH) {
                int il = wm + mt * 16 + (lane >> 2);
                S[(jl)     * MIRS + il]     = __float2half_rn(o00);
                S[(jl + 1) * MIRS + il]     = __float2half_rn(o01);
                S[(jl)     * MIRS + il + 8] = __float2half_rn(o10);
                S[(jl + 1) * MIRS + il + 8] = __float2half_rn(o11);
            }
        }
    }

    if (low0 || low1) {
        __syncthreads();
        int jl = tid;
        bool rowLow = (jl >> 7) ? low1 : low0;
        if (rowLow) {
            uint4* dst = (uint4*)&g_sqd[(size_t)(col0 + jl) * NPTS + row0];
            const uint4* srcp = (const uint4*)&S[jl * MIRS];
            #pragma unroll
            for (int q2 = 0; q2 < 16; q2++)
                dst[q2] = srcp[q2];
        }
    }
}

// ================= kernel 3: top-24 approx (fp16-domain scan) + exact rescoring =
__global__ __launch_bounds__(256)
void topk_curv_kernel(const float* __restrict__ E, const float* __restrict__ ref_curv) {
    const int row  = blockIdx.x * 8 + (threadIdx.x >> 5);
    const int lane = threadIdx.x & 31;
    const float INF = __int_as_float(0x7f800000);
    const uint4* r8 = (const uint4*)(g_sqd + (size_t)row * NPTS);

    // lanes 0..KEEP-1 hold the current KEEP smallest approx values, sorted.
    float lv = INF; int li = 0;
    float T  = INF;
    __half Th = __float2half(INF);

    #pragma unroll 1
    for (int it = 0; it < NPTS / 256; it++) {
        uint4 v = r8[it * 32 + lane];
        const __half2* hp = (const __half2*)&v;
        __half2 m01 = __hmin2(hp[0], hp[1]);
        __half2 m23 = __hmin2(hp[2], hp[3]);
        __half2 mm  = __hmin2(m01, m23);
        __half  m   = __hmin(__low2half(mm), __high2half(mm));
        unsigned ball = __ballot_sync(FULLM, __hlt(m, Th));
        while (ball) {
            int src = __ffs(ball) - 1;
            ball &= ball - 1;
            uint32_t w0 = __shfl_sync(FULLM, v.x, src);
            uint32_t w1 = __shfl_sync(FULLM, v.y, src);
            uint32_t w2 = __shfl_sync(FULLM, v.z, src);
            uint32_t w3 = __shfl_sync(FULLM, v.w, src);
            int jb = (it * 32 + src) * 8;
            uint32_t ww[4] = {w0, w1, w2, w3};
            #pragma unroll
            for (int h = 0; h < 4; h++) {
                float2 fp = __half22float2(*(const __half2*)&ww[h]);
                float pv2[2] = {fp.x, fp.y};
                #pragma unroll
                for (int c = 0; c < 2; c++) {
                    float val = pv2[c];
                    if (val < T) {                 // warp-uniform
                        unsigned less = __ballot_sync(FULLM, lv < val);
                        int pos = __popc(less);
                        float pv = __shfl_up_sync(FULLM, lv, 1);
                        int   pi = __shfl_up_sync(FULLM, li, 1);
                        if (lane == pos)                      { lv = val; li = jb + h * 2 + c; }
                        else if (lane > pos && lane < KEEP)   { lv = pv;  li = pi;             }
                        T = __shfl_sync(FULLM, lv, KEEP - 1);
                        Th = __float2half_ru(T);   // conservative (candidate set can only grow)
                    }
                }
            }
        }
    }

    // ---- exact fp32 rescoring of the KEEP candidates ----
    float4 x[4];
    const float4* Xr = (const float4*)&E[(size_t)row * DIM];
    #pragma unroll
    for (int q = 0; q < 4; q++) x[q] = Xr[q * 32 + lane];
    const float ni = g_norms[row];

    float exd = INF;
    #pragma unroll 1
    for (int c = 0; c < KEEP; c++) {
        int idx = __shfl_sync(FULLM, li, c);
        const float4* Y = (const float4*)&E[(size_t)idx * DIM];
        float s = 0.f;
        #pragma unroll
        for (int q = 0; q < 4; q++) {
            float4 y = Y[q * 32 + lane];
            s = fmaf(x[q].x, y.x, fmaf(x[q].y, y.y, fmaf(x[q].z, y.z, fmaf(x[q].w, y.w, s))));
        }
        #pragma unroll
        for (int o = 16; o; o >>= 1) s += __shfl_xor_sync(FULLM, s, o);
        if (lane == c) exd = fmaxf(ni + g_norms[idx] - 2.f * s, 0.f);
    }

    // ---- extract 15 smallest exact values (sorted), with indices ----
    float cur = exd;     // INF for lanes >= KEEP
    float myd = 0.f; int myi = 0;
    #pragma unroll 1
    for (int s = 0; s < KNN; s++) {
        float m = cur; int src = lane;
        #pragma unroll
        for (int o = 16; o; o >>= 1) {
            float om = __shfl_xor_sync(FULLM, m, o);
            int   os = __shfl_xor_sync(FULLM, src, o);
            if (om < m || (om == m && os < src)) { m = om; src = os; }
        }
        int wi = __shfl_sync(FULLM, li, src);
        if (lane == s) { myd = m; myi = wi; }
        if (lane == src) cur = INF;
    }

    // ---- curvature loss (exact, sorted ascending on lanes 0..14) ----
    float dd = (lane < KNN) ? sqrtf(fmaxf(myd, 1e-12f)) : 0.f;
    float ssum = dd;
    #pragma unroll
    for (int o = 16; o; o >>= 1) ssum += __shfl_xor_sync(FULLM, ssum, o);
    float mean = ssum / (float)KNN + 1e-8f;    // EPS_MEAN
    float df = 0.f;
    if (lane < KNN) {
        df = dd / mean - ref_curv[row * KNN + lane];
        g_knni[row * KNN + lane] = myi;
        g_knnd[row * 16 + lane]  = myd;
    }
    float l = df * df;
    #pragma unroll
    for (int o = 16; o; o >>= 1) l += __shfl_xor_sync(FULLM, l, o);
    if (lane == 0) atomicAdd(&g_acc[0], (double)l);
}

// ================= kernel 4: angular loss via Gram identity + rank sort =========
// dot(nb_j - x, nb_k - x) = G_jk - Gx_j - Gx_k + |x|^2, Gx_j = (|x|^2+|nb_j|^2-d_j^2)/2
__global__ __launch_bounds__(256)
void angular_kernel(const float* __restrict__ E, const float* __restrict__ ref_ang) {
    const int row  = blockIdx.x;
    const int tid  = threadIdx.x;
    const int lane = tid & 31;
    const int w    = tid >> 5;

    __shared__ float4 nbs[KNN * 128];   // raw neighbor rows (30 KB)
    __shared__ int   nidx[16];
    __shared__ float sGx[16];
    __shared__ float sD[16];
    __shared__ float cosv[NPAIR];
    __shared__ float lsum[8];

    if (tid < KNN) nidx[tid] = g_knni[row * KNN + tid];
    __syncthreads();

    const float ni = g_norms[row];
    // gather 15 neighbor rows (coalesced float4)
    for (int q = tid; q < KNN * 128; q += 256) {
        int j = q >> 7, c = q & 127;
        nbs[q] = ((const float4*)(E + (size_t)nidx[j] * DIM))[c];
    }
    if (tid < KNN) {
        float d2 = g_knnd[row * 16 + tid];
        float nj = g_norms[nidx[tid]];
        sGx[tid] = 0.5f * (ni + nj - d2);
        sD[tid]  = fmaxf(sqrtf(fmaxf(d2, 0.f)), 1e-8f);   // EPS_NORM
    }
    __syncthreads();

    // 105 pairwise dots of raw neighbors, combined via Gram identity
    for (int p = w; p < NPAIR; p += 8) {
        int jj = 0, rem = p;
        while (rem >= (KNN - 1) - jj) { rem -= (KNN - 1) - jj; jj++; }
        int kk = jj + 1 + rem;
        const float4* vj = &nbs[jj * 128];
        const float4* vk = &nbs[kk * 128];
        float s = 0.f;
        #pragma unroll
        for (int c4 = lane; c4 < 128; c4 += 32) {
            float4 a = vj[c4], b = vk[c4];
            s = fmaf(a.x, b.x, fmaf(a.y, b.y, fmaf(a.z, b.z, fmaf(a.w, b.w, s))));
        }
        #pragma unroll
        for (int o = 16; o; o >>= 1) s += __shfl_xor_sync(FULLM, s, o);
        if (!lane)
            cosv[p] = (s - sGx[jj] - sGx[kk] + ni) / (sD[jj] * sD[kk]);
    }
    __syncthreads();

    // rank-by-counting sort + MSE against sorted reference (single barrier)
    float part = 0.f;
    if (tid < NPAIR) {
        float mine = cosv[tid];
        int rank = 0;
        #pragma unroll 1
        for (int u = 0; u < NPAIR; u++) {
            float o = cosv[u];
            rank += (o < mine) || (o == mine && u < tid);
        }
        float df = mine - ref_ang[(size_t)row * NPAIR + rank];
        part = df * df;
    }
    #pragma unroll
    for (int o = 16; o; o >>= 1) part += __shfl_xor_sync(FULLM, part, o);
    if (!lane) lsum[w] = part;
    __syncthreads();
    if (tid == 0) {
        float t2 = 0.f;
        #pragma unroll
        for (int q = 0; q < 8; q++) t2 += lsum[q];
        atomicAdd(&g_acc[1], (double)t2);
    }
}

// ================= kernel 5: finalize =================
__global__ void finalize_kernel(float* out) {
    double curv = g_acc[0] / ((double)NPTS * KNN);
    double ang  = g_acc[1] / ((double)NPTS * NPAIR);
    out[0] = (float)(0.3 * curv + 0.7 * ang);
}

// ================= launch =================
extern "C" void kernel_launch(void* const* d_in, const int* in_sizes, int n_in,
                              void* d_out, int out_size) {
    const float* emb      = (const float*)d_in[0];
    const float* ref_curv = (const float*)d_in[1];
    const float* ref_ang  = (const float*)d_in[2];
    float* out = (float*)d_out;

    cudaFuncSetAttribute(gemm_bf16_kernel,
                         cudaFuncAttributeMaxDynamicSharedMemorySize, SMEM_GEMM);

    const int NTILES = 1056;   // sum over r of (floor(r/2)+1), r in 0..63

    zero_acc_kernel<<<1, 1>>>();
    prep_kernel<<<NPTS / 8, 256>>>(emb);
    gemm_bf16_kernel<<<NTILES, 256, SMEM_GEMM>>>();
    topk_curv_kernel<<<NPTS / 8, 256>>>(emb, ref_curv);
    angular_kernel<<<NPTS, 256>>>(emb, ref_ang);
    finalize_kernel<<<1, 1>>>(out);
}

// round 14
// speedup vs baseline: 1.0655x; 1.0655x over previous
#include <cuda_runtime.h>
#include <cuda_bf16.h>
#include <cuda_fp16.h>
#include <math.h>
#include <stdint.h>

// Problem constants
#define NPTS 8192
#define DIM  512
#define KNN  15
#define KEEP 24     // approx candidates kept per row (margin for bf16+fp16 error)
#define NPAIR 105   // 15*14/2
#define FULLM 0xFFFFFFFFu

// ---------------- scratch (device globals: no allocation allowed) -------------
__device__ __align__(16) __half g_sqd[(size_t)NPTS * NPTS];      // 128 MB approx sq dists
__device__ float  g_norms[NPTS];
__device__ __align__(16) __nv_bfloat16 g_H[(size_t)NPTS * DIM];  // bf16 embeddings
__device__ int    g_knni[NPTS * KNN];
__device__ double g_acc[2];                        // [0]=curv sumsq, [1]=ang sumsq

// ================= PTX helpers (generic sm_80+ only; NO tcgen05) =================
__device__ __forceinline__ uint32_t smem_u32(const void* p) {
    uint32_t a;
    asm("{ .reg .u64 t; cvta.to.shared.u64 t, %1; cvt.u32.u64 %0, t; }" : "=r"(a) : "l"(p));
    return a;
}
__device__ __forceinline__ void cp_async16(uint32_t dst, const void* src) {
    asm volatile("cp.async.cg.shared.global [%0], [%1], 16;" :: "r"(dst), "l"(src));
}
#define CP_COMMIT() asm volatile("cp.async.commit_group;" ::: "memory")

__device__ __forceinline__ void ldmat4(uint32_t* r, uint32_t saddr) {
    asm volatile("ldmatrix.sync.aligned.m8n8.x4.shared.b16 {%0,%1,%2,%3}, [%4];"
                 : "=r"(r[0]), "=r"(r[1]), "=r"(r[2]), "=r"(r[3]) : "r"(saddr));
}
__device__ __forceinline__ void mma_bf16(float* d, const uint32_t* a,
                                         uint32_t b0, uint32_t b1) {
    asm volatile(
        "mma.sync.aligned.m16n8k16.row.col.f32.bf16.bf16.f32 "
        "{%0,%1,%2,%3}, {%4,%5,%6,%7}, {%8,%9}, {%0,%1,%2,%3};"
        : "+f"(d[0]), "+f"(d[1]), "+f"(d[2]), "+f"(d[3])
        : "r"(a[0]), "r"(a[1]), "r"(a[2]), "r"(a[3]), "r"(b0), "r"(b1));
}

// ================= kernel 0: zero accumulators =================
__global__ void zero_acc_kernel() {
    g_acc[0] = 0.0; g_acc[1] = 0.0;
}

// ================= kernel 1: norms (fp32) + bf16 convert, one read of E ========
__global__ void prep_kernel(const float* __restrict__ E) {
    int row  = blockIdx.x * 8 + (threadIdx.x >> 5);
    int lane = threadIdx.x & 31;
    const float4* r = (const float4*)(E + (size_t)row * DIM);
    __nv_bfloat162* H2 = (__nv_bfloat162*)(g_H + (size_t)row * DIM);
    float s = 0.f;
    #pragma unroll
    for (int c4 = lane; c4 < DIM / 4; c4 += 32) {
        float4 v = r[c4];
        s = fmaf(v.x, v.x, fmaf(v.y, v.y, fmaf(v.z, v.z, fmaf(v.w, v.w, s))));
        H2[c4 * 2]     = __floats2bfloat162_rn(v.x, v.y);
        H2[c4 * 2 + 1] = __floats2bfloat162_rn(v.z, v.w);
    }
    #pragma unroll
    for (int o = 16; o; o >>= 1) s += __shfl_xor_sync(FULLM, s, o);
    if (!lane) g_norms[row] = s;
}

// ================= kernel 2: bf16 mma.sync Gram -> approx sq dists (fp16) =======
// CTA tile 128x256, BK=32, 8 warps @ 64x64, fp32 accum. Triangular 2c<=r grid.
#define SROW 80                 // 64B data + 16B pad per K-slab row
#define STAGEB (384 * SROW)     // A(128 rows) + B(256 rows) = 30720 B
#define MIRS 136                // S transpose stride (halves)
#define SMEM_GEMM (256 * MIRS * 2 > 2 * STAGEB ? 256 * MIRS * 2 : 2 * STAGEB)  // 69632

__global__ void __launch_bounds__(256, 1) gemm_bf16_kernel() {
    extern __shared__ __align__(128) char sbuf[];
    const uint32_t sb = smem_u32(sbuf);
    const int tid  = threadIdx.x;
    const int lane = tid & 31;
    const int wid  = tid >> 5;

    // triangular decode at (r:128-row, c:256-col) granularity: 2c <= r
    int t = blockIdx.x;
    int r = 2 * (int)sqrtf((float)t);
    if (r > 63) r = 63;
    #pragma unroll 1
    while (r < 63) {
        int rn = r + 1, m = rn >> 1;
        int cm = (rn & 1) ? (m + 1) * (m + 1) : m * m + m;
        if (cm <= t) r = rn; else break;
    }
    #pragma unroll 1
    for (;;) {
        int m = r >> 1;
        int cm = (r & 1) ? (m + 1) * (m + 1) : m * m + m;
        if (cm > t) r--; else break;
    }
    int m0 = r >> 1;
    int cumr = (r & 1) ? (m0 + 1) * (m0 + 1) : m0 * m0 + m0;
    int c = t - cumr;

    const int row0 = r * 128, col0 = c * 256;
    const int wm = (wid >> 2) * 64;
    const int wn = (wid & 3) * 64;
    const int hw = wn >> 7;

    const bool low0 = (col0 + 128) <= row0;
    const bool low1 = (col0 + 256) <= row0;
    const bool upH  = hw ? (col0 + 128 > row0) : false;
    const bool lowH = hw ? low1 : low0;

    float d[4][8][4];
    #pragma unroll
    for (int mt = 0; mt < 4; mt++)
        #pragma unroll
        for (int nt = 0; nt < 8; nt++)
            #pragma unroll
            for (int q = 0; q < 4; q++) d[mt][nt][q] = 0.f;

    {
        uint32_t s0 = sb;
        #pragma unroll
        for (int i = 0; i < 6; i++) {
            int q = tid + i * 256;
            int rw = q >> 2, cc = q & 3;
            const __nv_bfloat16* src = (rw < 128)
                ? &g_H[(size_t)(row0 + rw) * DIM + cc * 8]
                : &g_H[(size_t)(col0 + rw - 128) * DIM + cc * 8];
            cp_async16(s0 + rw * SROW + cc * 16, src);
        }
        CP_COMMIT();
    }

    for (int st = 0; st < 16; st++) {
        if (st < 15) {
            int kk = (st + 1) * 32;
            uint32_t s1 = sb + ((st + 1) & 1) * STAGEB;
            #pragma unroll
            for (int i = 0; i < 6; i++) {
                int q = tid + i * 256;
                int rw = q >> 2, cc = q & 3;
                const __nv_bfloat16* src = (rw < 128)
                    ? &g_H[(size_t)(row0 + rw) * DIM + kk + cc * 8]
                    : &g_H[(size_t)(col0 + rw - 128) * DIM + kk + cc * 8];
                cp_async16(s1 + rw * SROW + cc * 16, src);
            }
            CP_COMMIT();
            asm volatile("cp.async.wait_group 1;" ::: "memory");
        } else {
            asm volatile("cp.async.wait_group 0;" ::: "memory");
        }
        __syncthreads();

        uint32_t aT = sb + (st & 1) * STAGEB;
        uint32_t bT = aT + 128 * SROW;
        #pragma unroll
        for (int ks = 0; ks < 2; ks++) {
            int kb = ks * 32;
            uint32_t aF[4][4], bF[4][4];
            #pragma unroll
            for (int mt = 0; mt < 4; mt++)
                ldmat4(aF[mt], aT + (wm + mt * 16 + (lane & 15)) * SROW + kb + (lane >> 4) * 16);
            #pragma unroll
            for (int g = 0; g < 4; g++)
                ldmat4(bF[g], bT + (wn + g * 16 + (lane & 15)) * SROW + kb + (lane >> 4) * 16);
            #pragma unroll
            for (int mt = 0; mt < 4; mt++)
                #pragma unroll
                for (int nt = 0; nt < 8; nt++)
                    mma_bf16(d[mt][nt], aF[mt], bF[nt >> 1][nt & 1], bF[nt >> 1][(nt & 1) + 2]);
        }
        __syncthreads();
    }

    // ---------------- epilogue ----------------
    const float INF = __int_as_float(0x7f800000);
    __half* S = (__half*)sbuf;

    #pragma unroll
    for (int mt = 0; mt < 4; mt++) {
        int i0 = row0 + wm + mt * 16 + (lane >> 2);
        int i1 = i0 + 8;
        float n0 = g_norms[i0], n1 = g_norms[i1];
        #pragma unroll
        for (int nt = 0; nt < 8; nt++) {
            int jl = wn + nt * 8 + (lane & 3) * 2;
            int j0 = col0 + jl;
            float ja = g_norms[j0], jb = g_norms[j0 + 1];
            float o00 = fmaxf(n0 + ja - 2.f * d[mt][nt][0], 0.f);
            float o01 = fmaxf(n0 + jb - 2.f * d[mt][nt][1], 0.f);
            float o10 = fmaxf(n1 + ja - 2.f * d[mt][nt][2], 0.f);
            float o11 = fmaxf(n1 + jb - 2.f * d[mt][nt][3], 0.f);
            if (i0 == j0)     o00 = INF;
            if (i0 == j0 + 1) o01 = INF;
            if (i1 == j0)     o10 = INF;
            if (i1 == j0 + 1) o11 = INF;
            if (!upH) {
                *(__half2*)&g_sqd[(size_t)i0 * NPTS + j0] = __floats2half2_rn(o00, o01);
                *(__half2*)&g_sqd[(size_t)i1 * NPTS + j0] = __floats2half2_rn(o10, o11);
            }
            if (lowH) {
                int il = wm + mt * 16 + (lane >> 2);
                S[(jl)     * MIRS + il]     = __float2half_rn(o00);
                S[(jl + 1) * MIRS + il]     = __float2half_rn(o01);
                S[(jl)     * MIRS + il + 8] = __float2half_rn(o10);
                S[(jl + 1) * MIRS + il + 8] = __float2half_rn(o11);
            }
        }
    }

    if (low0 || low1) {
        __syncthreads();
        int jl = tid;
        bool rowLow = (jl >> 7) ? low1 : low0;
        if (rowLow) {
            uint4* dst = (uint4*)&g_sqd[(size_t)(col0 + jl) * NPTS + row0];
            const uint4* srcp = (const uint4*)&S[jl * MIRS];
            #pragma unroll
            for (int q2 = 0; q2 < 16; q2++)
                dst[q2] = srcp[q2];
        }
    }
}

// ================= kernel 3: top-24 approx (MLP=4 scan) + exact rescoring =======
__global__ __launch_bounds__(256)
void topk_curv_kernel(const float* __restrict__ E, const float* __restrict__ ref_curv) {
    const int row  = blockIdx.x * 8 + (threadIdx.x >> 5);
    const int lane = threadIdx.x & 31;
    const float INF = __int_as_float(0x7f800000);
    const uint4* r8 = (const uint4*)(g_sqd + (size_t)row * NPTS);

    // lanes 0..KEEP-1 hold the current KEEP smallest approx values, sorted.
    float lv = INF; int li = 0;
    float T  = INF;
    __half Th = __float2half(INF);

    #pragma unroll 1
    for (int ob = 0; ob < NPTS / 1024; ob++) {     // 8 outer blocks of 4 chunks
        uint4 v[4];
        #pragma unroll
        for (int u = 0; u < 4; u++)                 // 4 independent 512B warp-loads
            v[u] = r8[(ob * 4 + u) * 32 + lane];

        #pragma unroll
        for (int u = 0; u < 4; u++) {
            const __half2* hp = (const __half2*)&v[u];
            __half2 m01 = __hmin2(hp[0], hp[1]);
            __half2 m23 = __hmin2(hp[2], hp[3]);
            __half2 mm  = __hmin2(m01, m23);
            __half  m   = __hmin(__low2half(mm), __high2half(mm));
            unsigned ball = __ballot_sync(FULLM, __hlt(m, Th));
            while (ball) {
                int src = __ffs(ball) - 1;
                ball &= ball - 1;
                uint32_t w0 = __shfl_sync(FULLM, v[u].x, src);
                uint32_t w1 = __shfl_sync(FULLM, v[u].y, src);
                uint32_t w2 = __shfl_sync(FULLM, v[u].z, src);
                uint32_t w3 = __shfl_sync(FULLM, v[u].w, src);
                int jb = ((ob * 4 + u) * 32 + src) * 8;
                uint32_t ww[4] = {w0, w1, w2, w3};
                #pragma unroll
                for (int h = 0; h < 4; h++) {
                    float2 fp = __half22float2(*(const __half2*)&ww[h]);
                    float pv2[2] = {fp.x, fp.y};
                    #pragma unroll
                    for (int c = 0; c < 2; c++) {
                        float val = pv2[c];
                        if (val < T) {                 // warp-uniform
                            unsigned less = __ballot_sync(FULLM, lv < val);
                            int pos = __popc(less);
                            float pv = __shfl_up_sync(FULLM, lv, 1);
                            int   pi = __shfl_up_sync(FULLM, li, 1);
                            if (lane == pos)                      { lv = val; li = jb + h * 2 + c; }
                            else if (lane > pos && lane < KEEP)   { lv = pv;  li = pi;             }
                            T = __shfl_sync(FULLM, lv, KEEP - 1);
                            Th = __float2half_ru(T);   // conservative threshold
                        }
                    }
                }
            }
        }
    }

    // ---- exact fp32 rescoring of the KEEP candidates ----
    float4 x[4];
    const float4* Xr = (const float4*)&E[(size_t)row * DIM];
    #pragma unroll
    for (int q = 0; q < 4; q++) x[q] = Xr[q * 32 + lane];
    const float ni = g_norms[row];

    float exd = INF;
    #pragma unroll 1
    for (int c = 0; c < KEEP; c++) {
        int idx = __shfl_sync(FULLM, li, c);
        const float4* Y = (const float4*)&E[(size_t)idx * DIM];
        float s = 0.f;
        #pragma unroll
        for (int q = 0; q < 4; q++) {
            float4 y = Y[q * 32 + lane];
            s = fmaf(x[q].x, y.x, fmaf(x[q].y, y.y, fmaf(x[q].z, y.z, fmaf(x[q].w, y.w, s))));
        }
        #pragma unroll
        for (int o = 16; o; o >>= 1) s += __shfl_xor_sync(FULLM, s, o);
        if (lane == c) exd = fmaxf(ni + g_norms[idx] - 2.f * s, 0.f);
    }

    // ---- extract 15 smallest exact values (sorted), with indices ----
    float cur = exd;     // INF for lanes >= KEEP
    float myd = 0.f; int myi = 0;
    #pragma unroll 1
    for (int s = 0; s < KNN; s++) {
        float m = cur; int src = lane;
        #pragma unroll
        for (int o = 16; o; o >>= 1) {
            float om = __shfl_xor_sync(FULLM, m, o);
            int   os = __shfl_xor_sync(FULLM, src, o);
            if (om < m || (om == m && os < src)) { m = om; src = os; }
        }
        int wi = __shfl_sync(FULLM, li, src);
        if (lane == s) { myd = m; myi = wi; }
        if (lane == src) cur = INF;
    }

    // ---- curvature loss (exact, sorted ascending on lanes 0..14) ----
    float dd = (lane < KNN) ? sqrtf(fmaxf(myd, 1e-12f)) : 0.f;
    float ssum = dd;
    #pragma unroll
    for (int o = 16; o; o >>= 1) ssum += __shfl_xor_sync(FULLM, ssum, o);
    float mean = ssum / (float)KNN + 1e-8f;    // EPS_MEAN
    float df = 0.f;
    if (lane < KNN) {
        df = dd / mean - ref_curv[row * KNN + lane];
        g_knni[row * KNN + lane] = myi;
    }
    float l = df * df;
    #pragma unroll
    for (int o = 16; o; o >>= 1) l += __shfl_xor_sync(FULLM, l, o);
    if (lane == 0) atomicAdd(&g_acc[0], (double)l);
}

// ================= kernel 4: angular signature loss (R12 proven version) ========
__global__ __launch_bounds__(256)
void angular_kernel(const float* __restrict__ E, const float* __restrict__ ref_ang) {
    const int row  = blockIdx.x;
    const int tid  = threadIdx.x;
    const int lane = tid & 31;
    const int w    = tid >> 5;

    __shared__ float ei[DIM];
    __shared__ float vh[KNN][DIM];
    __shared__ float nrm[KNN];
    __shared__ float cosv[128];
    __shared__ float lsum[8];

    if (tid < 128) {
        float4 q = *(const float4*)&E[(size_t)row * DIM + tid * 4];
        *(float4*)&ei[tid * 4] = q;
    }
    if (tid >= 105 && tid < 128) cosv[tid] = __int_as_float(0x7f800000);
    __syncthreads();

    for (int j = w; j < KNN; j += 8) {
        int nb = g_knni[row * KNN + j];
        const float4* src = (const float4*)&E[(size_t)nb * DIM];
        float s = 0.f;
        for (int c4 = lane; c4 < DIM / 4; c4 += 32) {
            float4 q = src[c4];
            float4 e = *(const float4*)&ei[c4 * 4];
            float4 v; v.x = q.x - e.x; v.y = q.y - e.y; v.z = q.z - e.z; v.w = q.w - e.w;
            *(float4*)&vh[j][c4 * 4] = v;
            s = fmaf(v.x, v.x, fmaf(v.y, v.y, fmaf(v.z, v.z, fmaf(v.w, v.w, s))));
        }
        #pragma unroll
        for (int o = 16; o; o >>= 1) s += __shfl_xor_sync(FULLM, s, o);
        if (!lane) nrm[j] = fmaxf(sqrtf(s), 1e-8f);   // EPS_NORM
    }
    __syncthreads();

    for (int p = w; p < NPAIR; p += 8) {
        int jj = 0, rem = p;
        while (rem >= (KNN - 1) - jj) { rem -= (KNN - 1) - jj; jj++; }
        int kk = jj + 1 + rem;
        float s = 0.f;
        for (int c = lane; c < DIM; c += 32)
            s = fmaf(vh[jj][c], vh[kk][c], s);
        #pragma unroll
        for (int o = 16; o; o >>= 1) s += __shfl_xor_sync(FULLM, s, o);
        if (!lane) cosv[p] = s / (nrm[jj] * nrm[kk]);
    }
    __syncthreads();

    for (int k = 2; k <= 128; k <<= 1) {
        for (int j2 = k >> 1; j2 > 0; j2 >>= 1) {
            if (tid < 128) {
                int ixj = tid ^ j2;
                if (ixj > tid) {
                    float a = cosv[tid], b = cosv[ixj];
                    bool up = ((tid & k) == 0);
                    if ((a > b) == up) { cosv[tid] = b; cosv[ixj] = a; }
                }
            }
            __syncthreads();
        }
    }

    float s = 0.f;
    for (int t2 = tid; t2 < NPAIR; t2 += 256) {
        float df = cosv[t2] - ref_ang[(size_t)row * NPAIR + t2];
        s = fmaf(df, df, s);
    }
    #pragma unroll
    for (int o = 16; o; o >>= 1) s += __shfl_xor_sync(FULLM, s, o);
    if (!lane) lsum[w] = s;
    __syncthreads();
    if (tid == 0) {
        float t2 = 0.f;
        #pragma unroll
        for (int q = 0; q < 8; q++) t2 += lsum[q];
        atomicAdd(&g_acc[1], (double)t2);
    }
}

// ================= kernel 5: finalize =================
__global__ void finalize_kernel(float* out) {
    double curv = g_acc[0] / ((double)NPTS * KNN);
    double ang  = g_acc[1] / ((double)NPTS * NPAIR);
    out[0] = (float)(0.3 * curv + 0.7 * ang);
}

// ================= launch =================
extern "C" void kernel_launch(void* const* d_in, const int* in_sizes, int n_in,
                              void* d_out, int out_size) {
    const float* emb      = (const float*)d_in[0];
    const float* ref_curv = (const float*)d_in[1];
    const float* ref_ang  = (const float*)d_in[2];
    float* out = (float*)d_out;

    cudaFuncSetAttribute(gemm_bf16_kernel,
                         cudaFuncAttributeMaxDynamicSharedMemorySize, SMEM_GEMM);

    const int NTILES = 1056;   // sum over r of (floor(r/2)+1), r in 0..63

    zero_acc_kernel<<<1, 1>>>();
    prep_kernel<<<NPTS / 8, 256>>>(emb);
    gemm_bf16_kernel<<<NTILES, 256, SMEM_GEMM>>>();
    topk_curv_kernel<<<NPTS / 8, 256>>>(emb, ref_curv);
    angular_kernel<<<NPTS, 256>>>(emb, ref_ang);
    finalize_kernel<<<1, 1>>>(out);
}

// round 15
// speedup vs baseline: 1.1197x; 1.0508x over previous
#include <cuda_runtime.h>
#include <cuda_bf16.h>
#include <cuda_fp16.h>
#include <math.h>
#include <stdint.h>

// Problem constants
#define NPTS 8192
#define DIM  512
#define KNN  15
#define KEEP 24     // approx candidates kept per row (margin for bf16+fp16 error)
#define NPAIR 105   // 15*14/2
#define FULLM 0xFFFFFFFFu

// ---------------- scratch (device globals: no allocation allowed) -------------
__device__ __align__(16) __half g_sqd[(size_t)NPTS * NPTS];      // 128 MB approx sq dists
__device__ __align__(16) __half g_cmin[(size_t)NPTS * 256];      // 4 MB chunk minima
__device__ float  g_norms[NPTS];
__device__ __align__(16) __nv_bfloat16 g_H[(size_t)NPTS * DIM];  // bf16 embeddings
__device__ int    g_knni[NPTS * KNN];
__device__ double g_acc[2];                        // [0]=curv sumsq, [1]=ang sumsq

// ================= PTX helpers (generic sm_80+ only; NO tcgen05) =================
__device__ __forceinline__ uint32_t smem_u32(const void* p) {
    uint32_t a;
    asm("{ .reg .u64 t; cvta.to.shared.u64 t, %1; cvt.u32.u64 %0, t; }" : "=r"(a) : "l"(p));
    return a;
}
__device__ __forceinline__ void cp_async16(uint32_t dst, const void* src) {
    asm volatile("cp.async.cg.shared.global [%0], [%1], 16;" :: "r"(dst), "l"(src));
}
#define CP_COMMIT() asm volatile("cp.async.commit_group;" ::: "memory")

__device__ __forceinline__ void ldmat4(uint32_t* r, uint32_t saddr) {
    asm volatile("ldmatrix.sync.aligned.m8n8.x4.shared.b16 {%0,%1,%2,%3}, [%4];"
                 : "=r"(r[0]), "=r"(r[1]), "=r"(r[2]), "=r"(r[3]) : "r"(saddr));
}
__device__ __forceinline__ void mma_bf16(float* d, const uint32_t* a,
                                         uint32_t b0, uint32_t b1) {
    asm volatile(
        "mma.sync.aligned.m16n8k16.row.col.f32.bf16.bf16.f32 "
        "{%0,%1,%2,%3}, {%4,%5,%6,%7}, {%8,%9}, {%0,%1,%2,%3};"
        : "+f"(d[0]), "+f"(d[1]), "+f"(d[2]), "+f"(d[3])
        : "r"(a[0]), "r"(a[1]), "r"(a[2]), "r"(a[3]), "r"(b0), "r"(b1));
}
__device__ __forceinline__ float hmin8f(uint4 v) {
    __half2* hp = (__half2*)&v;
    __half2 m = __hmin2(__hmin2(hp[0], hp[1]), __hmin2(hp[2], hp[3]));
    return __half2float(__hmin(__low2half(m), __high2half(m)));
}
// warp-cooperative sorted top-KEEP insert (val warp-uniform)
__device__ __forceinline__ void wins_insert(float val, int gidx,
                                            float& lv, int& li, float& T, int lane) {
    if (val < T) {
        unsigned less = __ballot_sync(FULLM, lv < val);
        int pos = __popc(less);
        float pv = __shfl_up_sync(FULLM, lv, 1);
        int   pi = __shfl_up_sync(FULLM, li, 1);
        if (lane == pos)                    { lv = val; li = gidx; }
        else if (lane > pos && lane < KEEP) { lv = pv;  li = pi;   }
        T = __shfl_sync(FULLM, lv, KEEP - 1);
    }
}
// broadcast src lane's uint4 (8 halves) and insert its values
__device__ __forceinline__ void process_u4(uint4 v, int src, int jb,
                                           float& lv, int& li, float& T, int lane) {
    uint32_t ww[4];
    ww[0] = __shfl_sync(FULLM, v.x, src);
    ww[1] = __shfl_sync(FULLM, v.y, src);
    ww[2] = __shfl_sync(FULLM, v.z, src);
    ww[3] = __shfl_sync(FULLM, v.w, src);
    #pragma unroll
    for (int h = 0; h < 4; h++) {
        float2 fp = __half22float2(*(const __half2*)&ww[h]);
        wins_insert(fp.x, jb + h * 2,     lv, li, T, lane);
        wins_insert(fp.y, jb + h * 2 + 1, lv, li, T, lane);
    }
}

// ================= kernel 0: zero accumulators =================
__global__ void zero_acc_kernel() {
    g_acc[0] = 0.0; g_acc[1] = 0.0;
}

// ================= kernel 1: norms (fp32) + bf16 convert, one read of E ========
__global__ void prep_kernel(const float* __restrict__ E) {
    int row  = blockIdx.x * 8 + (threadIdx.x >> 5);
    int lane = threadIdx.x & 31;
    const float4* r = (const float4*)(E + (size_t)row * DIM);
    __nv_bfloat162* H2 = (__nv_bfloat162*)(g_H + (size_t)row * DIM);
    float s = 0.f;
    #pragma unroll
    for (int c4 = lane; c4 < DIM / 4; c4 += 32) {
        float4 v = r[c4];
        s = fmaf(v.x, v.x, fmaf(v.y, v.y, fmaf(v.z, v.z, fmaf(v.w, v.w, s))));
        H2[c4 * 2]     = __floats2bfloat162_rn(v.x, v.y);
        H2[c4 * 2 + 1] = __floats2bfloat162_rn(v.z, v.w);
    }
    #pragma unroll
    for (int o = 16; o; o >>= 1) s += __shfl_xor_sync(FULLM, s, o);
    if (!lane) g_norms[row] = s;
}

// ================= kernel 2: bf16 mma.sync Gram -> sq dists (fp16) + chunkmins ==
#define SROW 80                 // 64B data + 16B pad per K-slab row
#define STAGEB (384 * SROW)     // A(128 rows) + B(256 rows) = 30720 B
#define MIRS 136                // S transpose stride (halves)
#define SMEM_GEMM (256 * MIRS * 2 > 2 * STAGEB ? 256 * MIRS * 2 : 2 * STAGEB)  // 69632

__global__ void __launch_bounds__(256, 1) gemm_bf16_kernel() {
    extern __shared__ __align__(128) char sbuf[];
    const uint32_t sb = smem_u32(sbuf);
    const int tid  = threadIdx.x;
    const int lane = tid & 31;
    const int wid  = tid >> 5;

    // triangular decode at (r:128-row, c:256-col) granularity: 2c <= r
    int t = blockIdx.x;
    int r = 2 * (int)sqrtf((float)t);
    if (r > 63) r = 63;
    #pragma unroll 1
    while (r < 63) {
        int rn = r + 1, m = rn >> 1;
        int cm = (rn & 1) ? (m + 1) * (m + 1) : m * m + m;
        if (cm <= t) r = rn; else break;
    }
    #pragma unroll 1
    for (;;) {
        int m = r >> 1;
        int cm = (r & 1) ? (m + 1) * (m + 1) : m * m + m;
        if (cm > t) r--; else break;
    }
    int m0 = r >> 1;
    int cumr = (r & 1) ? (m0 + 1) * (m0 + 1) : m0 * m0 + m0;
    int c = t - cumr;

    const int row0 = r * 128, col0 = c * 256;
    const int wm = (wid >> 2) * 64;
    const int wn = (wid & 3) * 64;
    const int hw = wn >> 7;

    const bool low0 = (col0 + 128) <= row0;
    const bool low1 = (col0 + 256) <= row0;
    const bool upH  = hw ? (col0 + 128 > row0) : false;
    const bool lowH = hw ? low1 : low0;

    float d[4][8][4];
    #pragma unroll
    for (int mt = 0; mt < 4; mt++)
        #pragma unroll
        for (int nt = 0; nt < 8; nt++)
            #pragma unroll
            for (int q = 0; q < 4; q++) d[mt][nt][q] = 0.f;

    {
        uint32_t s0 = sb;
        #pragma unroll
        for (int i = 0; i < 6; i++) {
            int q = tid + i * 256;
            int rw = q >> 2, cc = q & 3;
            const __nv_bfloat16* src = (rw < 128)
                ? &g_H[(size_t)(row0 + rw) * DIM + cc * 8]
                : &g_H[(size_t)(col0 + rw - 128) * DIM + cc * 8];
            cp_async16(s0 + rw * SROW + cc * 16, src);
        }
        CP_COMMIT();
    }

    for (int st = 0; st < 16; st++) {
        if (st < 15) {
            int kk = (st + 1) * 32;
            uint32_t s1 = sb + ((st + 1) & 1) * STAGEB;
            #pragma unroll
            for (int i = 0; i < 6; i++) {
                int q = tid + i * 256;
                int rw = q >> 2, cc = q & 3;
                const __nv_bfloat16* src = (rw < 128)
                    ? &g_H[(size_t)(row0 + rw) * DIM + kk + cc * 8]
                    : &g_H[(size_t)(col0 + rw - 128) * DIM + kk + cc * 8];
                cp_async16(s1 + rw * SROW + cc * 16, src);
            }
            CP_COMMIT();
            asm volatile("cp.async.wait_group 1;" ::: "memory");
        } else {
            asm volatile("cp.async.wait_group 0;" ::: "memory");
        }
        __syncthreads();

        uint32_t aT = sb + (st & 1) * STAGEB;
        uint32_t bT = aT + 128 * SROW;
        #pragma unroll
        for (int ks = 0; ks < 2; ks++) {
            int kb = ks * 32;
            uint32_t aF[4][4], bF[4][4];
            #pragma unroll
            for (int mt = 0; mt < 4; mt++)
                ldmat4(aF[mt], aT + (wm + mt * 16 + (lane & 15)) * SROW + kb + (lane >> 4) * 16);
            #pragma unroll
            for (int g = 0; g < 4; g++)
                ldmat4(bF[g], bT + (wn + g * 16 + (lane & 15)) * SROW + kb + (lane >> 4) * 16);
            #pragma unroll
            for (int mt = 0; mt < 4; mt++)
                #pragma unroll
                for (int nt = 0; nt < 8; nt++)
                    mma_bf16(d[mt][nt], aF[mt], bF[nt >> 1][nt & 1], bF[nt >> 1][(nt & 1) + 2]);
        }
        __syncthreads();
    }

    // ---------------- epilogue ----------------
    const float INF = __int_as_float(0x7f800000);
    __half* S = (__half*)sbuf;

    #pragma unroll
    for (int mt = 0; mt < 4; mt++) {
        int i0 = row0 + wm + mt * 16 + (lane >> 2);
        int i1 = i0 + 8;
        float n0 = g_norms[i0], n1 = g_norms[i1];
        float cm2[2][2] = {{INF, INF}, {INF, INF}};   // [row 0/1][chunk 0/1]
        #pragma unroll
        for (int nt = 0; nt < 8; nt++) {
            int jl = wn + nt * 8 + (lane & 3) * 2;
            int j0 = col0 + jl;
            float ja = g_norms[j0], jb = g_norms[j0 + 1];
            float o00 = fmaxf(n0 + ja - 2.f * d[mt][nt][0], 0.f);
            float o01 = fmaxf(n0 + jb - 2.f * d[mt][nt][1], 0.f);
            float o10 = fmaxf(n1 + ja - 2.f * d[mt][nt][2], 0.f);
            float o11 = fmaxf(n1 + jb - 2.f * d[mt][nt][3], 0.f);
            if (i0 == j0)     o00 = INF;
            if (i0 == j0 + 1) o01 = INF;
            if (i1 == j0)     o10 = INF;
            if (i1 == j0 + 1) o11 = INF;
            int cg = nt >> 2;
            cm2[0][cg] = fminf(cm2[0][cg], fminf(o00, o01));
            cm2[1][cg] = fminf(cm2[1][cg], fminf(o10, o11));
            if (!upH) {
                *(__half2*)&g_sqd[(size_t)i0 * NPTS + j0] = __floats2half2_rn(o00, o01);
                *(__half2*)&g_sqd[(size_t)i1 * NPTS + j0] = __floats2half2_rn(o10, o11);
            }
            if (lowH) {
                int il = wm + mt * 16 + (lane >> 2);
                S[(jl)     * MIRS + il]     = __float2half_rn(o00);
                S[(jl + 1) * MIRS + il]     = __float2half_rn(o01);
                S[(jl)     * MIRS + il + 8] = __float2half_rn(o10);
                S[(jl + 1) * MIRS + il + 8] = __float2half_rn(o11);
            }
        }
        if (!upH) {
            #pragma unroll
            for (int rr = 0; rr < 2; rr++)
                #pragma unroll
                for (int cg = 0; cg < 2; cg++) {
                    float v = cm2[rr][cg];
                    v = fminf(v, __shfl_xor_sync(FULLM, v, 1));
                    v = fminf(v, __shfl_xor_sync(FULLM, v, 2));
                    if ((lane & 3) == 0)
                        g_cmin[(size_t)(rr ? i1 : i0) * 256 + ((col0 + wn) >> 5) + cg]
                            = __float2half_rn(v);
                }
        }
    }

    if (low0 || low1) {
        __syncthreads();
        int jl = tid;
        bool rowLow = (jl >> 7) ? low1 : low0;
        if (rowLow) {
            uint4* dst = (uint4*)&g_sqd[(size_t)(col0 + jl) * NPTS + row0];
            const uint4* srcp = (const uint4*)&S[jl * MIRS];
            const __half hinf = __ushort_as_half(0x7C00);
            #pragma unroll
            for (int g = 0; g < 4; g++) {
                __half2 m2 = __halves2half2(hinf, hinf);
                #pragma unroll
                for (int q2 = 0; q2 < 4; q2++) {
                    uint4 val = srcp[g * 4 + q2];
                    dst[g * 4 + q2] = val;
                    __half2* hp = (__half2*)&val;
                    m2 = __hmin2(m2, __hmin2(__hmin2(hp[0], hp[1]), __hmin2(hp[2], hp[3])));
                }
                g_cmin[(size_t)(col0 + jl) * 256 + (row0 >> 5) + g]
                    = __hmin(__low2half(m2), __high2half(m2));
            }
        }
    }
}

// ================= kernel 3: chunk-min pruned top-24 + exact rescoring ==========
__global__ __launch_bounds__(256)
void topk_curv_kernel(const float* __restrict__ E, const float* __restrict__ ref_curv) {
    const int row  = blockIdx.x * 8 + (threadIdx.x >> 5);
    const int lane = threadIdx.x & 31;
    const int wrp  = threadIdx.x >> 5;
    const float INF = __int_as_float(0x7f800000);

    __shared__ uint16_t cids_s[8][256];
    uint16_t* cids = cids_s[wrp];

    // ---- pass 1: T24 = 24th smallest chunk-min over this row's 256 chunks ----
    uint4 cmv = ((const uint4*)(g_cmin + (size_t)row * 256))[lane];
    float lv = INF; int li = 0; float T = INF;
    {
        float m = hmin8f(cmv);
        unsigned ball = __ballot_sync(FULLM, m < T);
        while (ball) {
            int src = __ffs(ball) - 1;
            ball &= ball - 1;
            process_u4(cmv, src, 0, lv, li, T, lane);
        }
    }
    const float T24 = __shfl_sync(FULLM, lv, KEEP - 1);

    // ---- select + compact chunks with min <= T24 ----
    unsigned selm = 0;
    {
        const __half* ch = (const __half*)&cmv;
        #pragma unroll
        for (int h = 0; h < 8; h++)
            if (__half2float(ch[h]) <= T24) selm |= 1u << h;
    }
    int base = 0;
    #pragma unroll
    for (int h = 0; h < 8; h++) {
        unsigned b = __ballot_sync(FULLM, (selm >> h) & 1);
        int pos = base + __popc(b & ((1u << lane) - 1));
        if ((selm >> h) & 1) cids[pos] = (uint16_t)(lane * 8 + h);
        base += __popc(b);
    }
    const int n_sel = base;
    __syncwarp();

    // ---- pass 2: reset list; insert values from selected chunks (8 chunks/batch)
    lv = INF; li = 0; T = INF;
    const uint4* rowp = (const uint4*)(g_sqd + (size_t)row * NPTS);
    const int nb = (n_sel + 7) >> 3;
    #pragma unroll 1
    for (int b = 0; b < nb; b++) {
        int slot = b * 8 + (lane >> 2);
        bool valid = slot < n_sel;
        int cid = valid ? (int)cids[slot] : 0;
        uint4 v = rowp[cid * 4 + (lane & 3)];
        float m = valid ? hmin8f(v) : INF;
        unsigned ball = __ballot_sync(FULLM, m < T);
        while (ball) {
            int src = __ffs(ball) - 1;
            ball &= ball - 1;
            int cs = __shfl_sync(FULLM, cid, src);
            process_u4(v, src, cs * 32 + (src & 3) * 8, lv, li, T, lane);
        }
    }

    // ---- exact fp32 rescoring of the KEEP candidates ----
    float4 x[4];
    const float4* Xr = (const float4*)&E[(size_t)row * DIM];
    #pragma unroll
    for (int q = 0; q < 4; q++) x[q] = Xr[q * 32 + lane];
    const float ni = g_norms[row];

    float exd = INF;
    #pragma unroll 1
    for (int c = 0; c < KEEP; c++) {
        int idx = __shfl_sync(FULLM, li, c);
        const float4* Y = (const float4*)&E[(size_t)idx * DIM];
        float s = 0.f;
        #pragma unroll
        for (int q = 0; q < 4; q++) {
            float4 y = Y[q * 32 + lane];
            s = fmaf(x[q].x, y.x, fmaf(x[q].y, y.y, fmaf(x[q].z, y.z, fmaf(x[q].w, y.w, s))));
        }
        #pragma unroll
        for (int o = 16; o; o >>= 1) s += __shfl_xor_sync(FULLM, s, o);
        if (lane == c) exd = fmaxf(ni + g_norms[idx] - 2.f * s, 0.f);
    }

    // ---- extract 15 smallest exact values (sorted), with indices ----
    float cur = exd;     // INF for lanes >= KEEP
    float myd = 0.f; int myi = 0;
    #pragma unroll 1
    for (int s = 0; s < KNN; s++) {
        float m = cur; int src = lane;
        #pragma unroll
        for (int o = 16; o; o >>= 1) {
            float om = __shfl_xor_sync(FULLM, m, o);
            int   os = __shfl_xor_sync(FULLM, src, o);
            if (om < m || (om == m && os < src)) { m = om; src = os; }
        }
        int wi = __shfl_sync(FULLM, li, src);
        if (lane == s) { myd = m; myi = wi; }
        if (lane == src) cur = INF;
    }

    // ---- curvature loss (exact, sorted ascending on lanes 0..14) ----
    float dd = (lane < KNN) ? sqrtf(fmaxf(myd, 1e-12f)) : 0.f;
    float ssum = dd;
    #pragma unroll
    for (int o = 16; o; o >>= 1) ssum += __shfl_xor_sync(FULLM, ssum, o);
    float mean = ssum / (float)KNN + 1e-8f;    // EPS_MEAN
    float df = 0.f;
    if (lane < KNN) {
        df = dd / mean - ref_curv[row * KNN + lane];
        g_knni[row * KNN + lane] = myi;
    }
    float l = df * df;
    #pragma unroll
    for (int o = 16; o; o >>= 1) l += __shfl_xor_sync(FULLM, l, o);
    if (lane == 0) atomicAdd(&g_acc[0], (double)l);
}

// ================= kernel 4: angular signature loss (R12 proven version) ========
__global__ __launch_bounds__(256)
void angular_kernel(const float* __restrict__ E, const float* __restrict__ ref_ang) {
    const int row  = blockIdx.x;
    const int tid  = threadIdx.x;
    const int lane = tid & 31;
    const int w    = tid >> 5;

    __shared__ float ei[DIM];
    __shared__ float vh[KNN][DIM];
    __shared__ float nrm[KNN];
    __shared__ float cosv[128];
    __shared__ float lsum[8];

    if (tid < 128) {
        float4 q = *(const float4*)&E[(size_t)row * DIM + tid * 4];
        *(float4*)&ei[tid * 4] = q;
    }
    if (tid >= 105 && tid < 128) cosv[tid] = __int_as_float(0x7f800000);
    __syncthreads();

    for (int j = w; j < KNN; j += 8) {
        int nb = g_knni[row * KNN + j];
        const float4* src = (const float4*)&E[(size_t)nb * DIM];
        float s = 0.f;
        for (int c4 = lane; c4 < DIM / 4; c4 += 32) {
            float4 q = src[c4];
            float4 e = *(const float4*)&ei[c4 * 4];
            float4 v; v.x = q.x - e.x; v.y = q.y - e.y; v.z = q.z - e.z; v.w = q.w - e.w;
            *(float4*)&vh[j][c4 * 4] = v;
            s = fmaf(v.x, v.x, fmaf(v.y, v.y, fmaf(v.z, v.z, fmaf(v.w, v.w, s))));
        }
        #pragma unroll
        for (int o = 16; o; o >>= 1) s += __shfl_xor_sync(FULLM, s, o);
        if (!lane) nrm[j] = fmaxf(sqrtf(s), 1e-8f);   // EPS_NORM
    }
    __syncthreads();

    for (int p = w; p < NPAIR; p += 8) {
        int jj = 0, rem = p;
        while (rem >= (KNN - 1) - jj) { rem -= (KNN - 1) - jj; jj++; }
        int kk = jj + 1 + rem;
        float s = 0.f;
        for (int c = lane; c < DIM; c += 32)
            s = fmaf(vh[jj][c], vh[kk][c], s);
        #pragma unroll
        for (int o = 16; o; o >>= 1) s += __shfl_xor_sync(FULLM, s, o);
        if (!lane) cosv[p] = s / (nrm[jj] * nrm[kk]);
    }
    __syncthreads();

    for (int k = 2; k <= 128; k <<= 1) {
        for (int j2 = k >> 1; j2 > 0; j2 >>= 1) {
            if (tid < 128) {
                int ixj = tid ^ j2;
                if (ixj > tid) {
                    float a = cosv[tid], b = cosv[ixj];
                    bool up = ((tid & k) == 0);
                    if ((a > b) == up) { cosv[tid] = b; cosv[ixj] = a; }
                }
            }
            __syncthreads();
        }
    }

    float s = 0.f;
    for (int t2 = tid; t2 < NPAIR; t2 += 256) {
        float df = cosv[t2] - ref_ang[(size_t)row * NPAIR + t2];
        s = fmaf(df, df, s);
    }
    #pragma unroll
    for (int o = 16; o; o >>= 1) s += __shfl_xor_sync(FULLM, s, o);
    if (!lane) lsum[w] = s;
    __syncthreads();
    if (tid == 0) {
        float t2 = 0.f;
        #pragma unroll
        for (int q = 0; q < 8; q++) t2 += lsum[q];
        atomicAdd(&g_acc[1], (double)t2);
    }
}

// ================= kernel 5: finalize =================
__global__ void finalize_kernel(float* out) {
    double curv = g_acc[0] / ((double)NPTS * KNN);
    double ang  = g_acc[1] / ((double)NPTS * NPAIR);
    out[0] = (float)(0.3 * curv + 0.7 * ang);
}

// ================= launch =================
extern "C" void kernel_launch(void* const* d_in, const int* in_sizes, int n_in,
                              void* d_out, int out_size) {
    const float* emb      = (const float*)d_in[0];
    const float* ref_curv = (const float*)d_in[1];
    const float* ref_ang  = (const float*)d_in[2];
    float* out = (float*)d_out;

    cudaFuncSetAttribute(gemm_bf16_kernel,
                         cudaFuncAttributeMaxDynamicSharedMemorySize, SMEM_GEMM);

    const int NTILES = 1056;   // sum over r of (floor(r/2)+1), r in 0..63

    zero_acc_kernel<<<1, 1>>>();
    prep_kernel<<<NPTS / 8, 256>>>(emb);
    gemm_bf16_kernel<<<NTILES, 256, SMEM_GEMM>>>();
    topk_curv_kernel<<<NPTS / 8, 256>>>(emb, ref_curv);
    angular_kernel<<<NPTS, 256>>>(emb, ref_ang);
    finalize_kernel<<<1, 1>>>(out);
}

// round 17
// speedup vs baseline: 1.2213x; 1.0907x over previous
#include <cuda_runtime.h>
#include <cuda_bf16.h>
#include <cuda_fp16.h>
#include <math.h>
#include <stdint.h>

// Problem constants
#define NPTS 8192
#define DIM  512
#define KNN  15
#define KEEP 24     // approx candidates kept per row (margin for bf16+fp16 error)
#define NPAIR 105   // 15*14/2
#define FULLM 0xFFFFFFFFu

// ---------------- scratch (device globals: no allocation allowed) -------------
__device__ __align__(16) __half g_sqd[(size_t)NPTS * NPTS];      // 128 MB approx sq dists
__device__ __align__(16) __half g_cmin[(size_t)NPTS * 256];      // 4 MB chunk minima
__device__ float  g_norms[NPTS];
__device__ __align__(16) __nv_bfloat16 g_H[(size_t)NPTS * DIM];  // bf16 embeddings
__device__ int    g_knni[NPTS * KNN];
__device__ double g_acc[2];                        // [0]=curv sumsq, [1]=ang sumsq

// ================= PTX helpers (generic sm_80+ only; NO tcgen05) =================
__device__ __forceinline__ uint32_t smem_u32(const void* p) {
    uint32_t a;
    asm("{ .reg .u64 t; cvta.to.shared.u64 t, %1; cvt.u32.u64 %0, t; }" : "=r"(a) : "l"(p));
    return a;
}
__device__ __forceinline__ void cp_async16(uint32_t dst, const void* src) {
    asm volatile("cp.async.cg.shared.global [%0], [%1], 16;" :: "r"(dst), "l"(src));
}
#define CP_COMMIT() asm volatile("cp.async.commit_group;" ::: "memory")

__device__ __forceinline__ void ldmat4(uint32_t* r, uint32_t saddr) {
    asm volatile("ldmatrix.sync.aligned.m8n8.x4.shared.b16 {%0,%1,%2,%3}, [%4];"
                 : "=r"(r[0]), "=r"(r[1]), "=r"(r[2]), "=r"(r[3]) : "r"(saddr));
}
__device__ __forceinline__ void mma_bf16(float* d, const uint32_t* a,
                                         uint32_t b0, uint32_t b1) {
    asm volatile(
        "mma.sync.aligned.m16n8k16.row.col.f32.bf16.bf16.f32 "
        "{%0,%1,%2,%3}, {%4,%5,%6,%7}, {%8,%9}, {%0,%1,%2,%3};"
        : "+f"(d[0]), "+f"(d[1]), "+f"(d[2]), "+f"(d[3])
        : "r"(a[0]), "r"(a[1]), "r"(a[2]), "r"(a[3]), "r"(b0), "r"(b1));
}
__device__ __forceinline__ float hmin8f(uint4 v) {
    __half2* hp = (__half2*)&v;
    __half2 m = __hmin2(__hmin2(hp[0], hp[1]), __hmin2(hp[2], hp[3]));
    return __half2float(__hmin(__low2half(m), __high2half(m)));
}
// warp-cooperative sorted top-KEEP insert, threshold capped at Tcap
__device__ __forceinline__ void wins_insert_c(float val, int gidx, float Tcap,
                                              float& lv, int& li, float& T, int lane) {
    if (val < T) {
        unsigned less = __ballot_sync(FULLM, lv < val);
        int pos = __popc(less);
        float pv = __shfl_up_sync(FULLM, lv, 1);
        int   pi = __shfl_up_sync(FULLM, li, 1);
        if (lane == pos)                    { lv = val; li = gidx; }
        else if (lane > pos && lane < KEEP) { lv = pv;  li = pi;   }
        T = fminf(Tcap, __shfl_sync(FULLM, lv, KEEP - 1));
    }
}
// broadcast src lane's uint4 (8 halves) and insert its values (capped threshold)
__device__ __forceinline__ void process_u4c(uint4 v, int src, int jb, float Tcap,
                                            float& lv, int& li, float& T, int lane) {
    uint32_t ww[4];
    ww[0] = __shfl_sync(FULLM, v.x, src);
    ww[1] = __shfl_sync(FULLM, v.y, src);
    ww[2] = __shfl_sync(FULLM, v.z, src);
    ww[3] = __shfl_sync(FULLM, v.w, src);
    #pragma unroll
    for (int h = 0; h < 4; h++) {
        float2 fp = __half22float2(*(const __half2*)&ww[h]);
        wins_insert_c(fp.x, jb + h * 2,     Tcap, lv, li, T, lane);
        wins_insert_c(fp.y, jb + h * 2 + 1, Tcap, lv, li, T, lane);
    }
}

// ================= kernel 1: norms (fp32) + bf16 convert + acc zero =============
__global__ void prep_kernel(const float* __restrict__ E) {
    if (blockIdx.x == 0 && threadIdx.x == 0) { g_acc[0] = 0.0; g_acc[1] = 0.0; }
    int row  = blockIdx.x * 8 + (threadIdx.x >> 5);
    int lane = threadIdx.x & 31;
    const float4* r = (const float4*)(E + (size_t)row * DIM);
    __nv_bfloat162* H2 = (__nv_bfloat162*)(g_H + (size_t)row * DIM);
    float s = 0.f;
    #pragma unroll
    for (int c4 = lane; c4 < DIM / 4; c4 += 32) {
        float4 v = r[c4];
        s = fmaf(v.x, v.x, fmaf(v.y, v.y, fmaf(v.z, v.z, fmaf(v.w, v.w, s))));
        H2[c4 * 2]     = __floats2bfloat162_rn(v.x, v.y);
        H2[c4 * 2 + 1] = __floats2bfloat162_rn(v.z, v.w);
    }
    #pragma unroll
    for (int o = 16; o; o >>= 1) s += __shfl_xor_sync(FULLM, s, o);
    if (!lane) g_norms[row] = s;
}

// ================= kernel 2: bf16 mma.sync Gram -> sq dists (fp16) + chunkmins ==
#define SROW 80                 // 64B data + 16B pad per K-slab row
#define STAGEB (384 * SROW)     // A(128 rows) + B(256 rows) = 30720 B
#define MIRS 136                // S transpose stride (halves)
#define SMEM_GEMM (256 * MIRS * 2 > 2 * STAGEB ? 256 * MIRS * 2 : 2 * STAGEB)  // 69632

__global__ void __launch_bounds__(256, 1) gemm_bf16_kernel() {
    extern __shared__ __align__(128) char sbuf[];
    const uint32_t sb = smem_u32(sbuf);
    const int tid  = threadIdx.x;
    const int lane = tid & 31;
    const int wid  = tid >> 5;

    // triangular decode at (r:128-row, c:256-col) granularity: 2c <= r
    int t = blockIdx.x;
    int r = 2 * (int)sqrtf((float)t);
    if (r > 63) r = 63;
    #pragma unroll 1
    while (r < 63) {
        int rn = r + 1, m = rn >> 1;
        int cm = (rn & 1) ? (m + 1) * (m + 1) : m * m + m;
        if (cm <= t) r = rn; else break;
    }
    #pragma unroll 1
    for (;;) {
        int m = r >> 1;
        int cm = (r & 1) ? (m + 1) * (m + 1) : m * m + m;
        if (cm > t) r--; else break;
    }
    int m0 = r >> 1;
    int cumr = (r & 1) ? (m0 + 1) * (m0 + 1) : m0 * m0 + m0;
    int c = t - cumr;

    const int row0 = r * 128, col0 = c * 256;
    const int wm = (wid >> 2) * 64;
    const int wn = (wid & 3) * 64;
    const int hw = wn >> 7;

    const bool low0 = (col0 + 128) <= row0;
    const bool low1 = (col0 + 256) <= row0;
    const bool upH  = hw ? (col0 + 128 > row0) : false;
    const bool lowH = hw ? low1 : low0;

    float d[4][8][4];
    #pragma unroll
    for (int mt = 0; mt < 4; mt++)
        #pragma unroll
        for (int nt = 0; nt < 8; nt++)
            #pragma unroll
            for (int q = 0; q < 4; q++) d[mt][nt][q] = 0.f;

    {
        uint32_t s0 = sb;
        #pragma unroll
        for (int i = 0; i < 6; i++) {
            int q = tid + i * 256;
            int rw = q >> 2, cc = q & 3;
            const __nv_bfloat16* src = (rw < 128)
                ? &g_H[(size_t)(row0 + rw) * DIM + cc * 8]
                : &g_H[(size_t)(col0 + rw - 128) * DIM + cc * 8];
            cp_async16(s0 + rw * SROW + cc * 16, src);
        }
        CP_COMMIT();
    }

    for (int st = 0; st < 16; st++) {
        if (st < 15) {
            int kk = (st + 1) * 32;
            uint32_t s1 = sb + ((st + 1) & 1) * STAGEB;
            #pragma unroll
            for (int i = 0; i < 6; i++) {
                int q = tid + i * 256;
                int rw = q >> 2, cc = q & 3;
                const __nv_bfloat16* src = (rw < 128)
                    ? &g_H[(size_t)(row0 + rw) * DIM + kk + cc * 8]
                    : &g_H[(size_t)(col0 + rw - 128) * DIM + kk + cc * 8];
                cp_async16(s1 + rw * SROW + cc * 16, src);
            }
            CP_COMMIT();
            asm volatile("cp.async.wait_group 1;" ::: "memory");
        } else {
            asm volatile("cp.async.wait_group 0;" ::: "memory");
        }
        __syncthreads();

        uint32_t aT = sb + (st & 1) * STAGEB;
        uint32_t bT = aT + 128 * SROW;
        #pragma unroll
        for (int ks = 0; ks < 2; ks++) {
            int kb = ks * 32;
            uint32_t aF[4][4], bF[4][4];
            #pragma unroll
            for (int mt = 0; mt < 4; mt++)
                ldmat4(aF[mt], aT + (wm + mt * 16 + (lane & 15)) * SROW + kb + (lane >> 4) * 16);
            #pragma unroll
            for (int g = 0; g < 4; g++)
                ldmat4(bF[g], bT + (wn + g * 16 + (lane & 15)) * SROW + kb + (lane >> 4) * 16);
            #pragma unroll
            for (int mt = 0; mt < 4; mt++)
                #pragma unroll
                for (int nt = 0; nt < 8; nt++)
                    mma_bf16(d[mt][nt], aF[mt], bF[nt >> 1][nt & 1], bF[nt >> 1][(nt & 1) + 2]);
        }
        __syncthreads();
    }

    // ---------------- epilogue ----------------
    const float INF = __int_as_float(0x7f800000);
    __half* S = (__half*)sbuf;

    #pragma unroll
    for (int mt = 0; mt < 4; mt++) {
        int i0 = row0 + wm + mt * 16 + (lane >> 2);
        int i1 = i0 + 8;
        float n0 = g_norms[i0], n1 = g_norms[i1];
        float cm2[2][2] = {{INF, INF}, {INF, INF}};   // [row 0/1][chunk 0/1]
        #pragma unroll
        for (int nt = 0; nt < 8; nt++) {
            int jl = wn + nt * 8 + (lane & 3) * 2;
            int j0 = col0 + jl;
            float ja = g_norms[j0], jb = g_norms[j0 + 1];
            float o00 = fmaxf(n0 + ja - 2.f * d[mt][nt][0], 0.f);
            float o01 = fmaxf(n0 + jb - 2.f * d[mt][nt][1], 0.f);
            float o10 = fmaxf(n1 + ja - 2.f * d[mt][nt][2], 0.f);
            float o11 = fmaxf(n1 + jb - 2.f * d[mt][nt][3], 0.f);
            if (i0 == j0)     o00 = INF;
            if (i0 == j0 + 1) o01 = INF;
            if (i1 == j0)     o10 = INF;
            if (i1 == j0 + 1) o11 = INF;
            int cg = nt >> 2;
            cm2[0][cg] = fminf(cm2[0][cg], fminf(o00, o01));
            cm2[1][cg] = fminf(cm2[1][cg], fminf(o10, o11));
            if (!upH) {
                *(__half2*)&g_sqd[(size_t)i0 * NPTS + j0] = __floats2half2_rn(o00, o01);
                *(__half2*)&g_sqd[(size_t)i1 * NPTS + j0] = __floats2half2_rn(o10, o11);
            }
            if (lowH) {
                int il = wm + mt * 16 + (lane >> 2);
                S[(jl)     * MIRS + il]     = __float2half_rn(o00);
                S[(jl + 1) * MIRS + il]     = __float2half_rn(o01);
                S[(jl)     * MIRS + il + 8] = __float2half_rn(o10);
                S[(jl + 1) * MIRS + il + 8] = __float2half_rn(o11);
            }
        }
        if (!upH) {
            #pragma unroll
            for (int rr = 0; rr < 2; rr++)
                #pragma unroll
                for (int cg = 0; cg < 2; cg++) {
                    float v = cm2[rr][cg];
                    v = fminf(v, __shfl_xor_sync(FULLM, v, 1));
                    v = fminf(v, __shfl_xor_sync(FULLM, v, 2));
                    if ((lane & 3) == 0)
                        g_cmin[(size_t)(rr ? i1 : i0) * 256 + ((col0 + wn) >> 5) + cg]
                            = __float2half_rn(v);
                }
        }
    }

    if (low0 || low1) {
        __syncthreads();
        int jl = tid;
        bool rowLow = (jl >> 7) ? low1 : low0;
        if (rowLow) {
            uint4* dst = (uint4*)&g_sqd[(size_t)(col0 + jl) * NPTS + row0];
            const uint4* srcp = (const uint4*)&S[jl * MIRS];
            const __half hinf = __ushort_as_half(0x7C00);
            #pragma unroll
            for (int g = 0; g < 4; g++) {
                __half2 m2 = __halves2half2(hinf, hinf);
                #pragma unroll
                for (int q2 = 0; q2 < 4; q2++) {
                    uint4 val = srcp[g * 4 + q2];
                    dst[g * 4 + q2] = val;
                    __half2* hp = (__half2*)&val;
                    m2 = __hmin2(m2, __hmin2(__hmin2(hp[0], hp[1]), __hmin2(hp[2], hp[3])));
                }
                g_cmin[(size_t)(col0 + jl) * 256 + (row0 >> 5) + g]
                    = __hmin(__low2half(m2), __high2half(m2));
            }
        }
    }
}

// ================= kernel 3: bisect-pruned top-24 + exact rescoring =============
__global__ __launch_bounds__(256)
void topk_curv_kernel(const float* __restrict__ E, const float* __restrict__ ref_curv) {
    const int row  = blockIdx.x * 8 + (threadIdx.x >> 5);
    const int lane = threadIdx.x & 31;
    const int wrp  = threadIdx.x >> 5;
    const float INF = __int_as_float(0x7f800000);

    __shared__ uint16_t cids_s[8][256];
    uint16_t* cids = cids_s[wrp];

    // ---- pass 1: binary search for u = smallest uint16 threshold with
    //      count(chunk-min bits <= u) >= KEEP. (fp16 positives order as uint16.)
    uint4 cmv = ((const uint4*)(g_cmin + (size_t)row * 256))[lane];
    uint32_t hb[4] = {cmv.x, cmv.y, cmv.z, cmv.w};
    uint32_t lo = 0, hi = 0x7BFF;
    #pragma unroll 1
    while (lo < hi) {
        uint32_t mid = (lo + hi) >> 1;
        int cnt = 0;
        #pragma unroll
        for (int i = 0; i < 4; i++) {
            cnt += ((hb[i] & 0xFFFFu) <= mid);
            cnt += ((hb[i] >> 16)     <= mid);
        }
        cnt = __reduce_add_sync(FULLM, cnt);
        if (cnt >= KEEP) hi = mid; else lo = mid + 1;
    }
    const uint32_t u = lo;   // >= KEEP chunk-mins <= u; rank-KEEP value <= u

    // ---- select + compact chunks with min-bits <= u ----
    unsigned selm = 0;
    #pragma unroll
    for (int i = 0; i < 4; i++) {
        if ((hb[i] & 0xFFFFu) <= u) selm |= 1u << (2 * i);
        if ((hb[i] >> 16)     <= u) selm |= 1u << (2 * i + 1);
    }
    int base = 0;
    #pragma unroll
    for (int h = 0; h < 8; h++) {
        unsigned b = __ballot_sync(FULLM, (selm >> h) & 1);
        int pos = base + __popc(b & ((1u << lane) - 1));
        if ((selm >> h) & 1) cids[pos] = (uint16_t)(lane * 8 + h);
        base += __popc(b);
    }
    const int n_sel = base;
    __syncwarp();

    // ---- pass 2: sorted top-KEEP insert seeded with tight threshold ----
    const float Tcap = __half2float(__ushort_as_half((unsigned short)(u + 1)));
    float lv = INF; int li = 0; float T = Tcap;
    const uint4* rowp = (const uint4*)(g_sqd + (size_t)row * NPTS);
    const int nb = (n_sel + 7) >> 3;
    #pragma unroll 1
    for (int b = 0; b < nb; b++) {
        int slot = b * 8 + (lane >> 2);
        bool valid = slot < n_sel;
        int cid = valid ? (int)cids[slot] : 0;
        uint4 v = rowp[cid * 4 + (lane & 3)];
        float m = valid ? hmin8f(v) : INF;
        unsigned ball = __ballot_sync(FULLM, m < T);
        while (ball) {
            int src = __ffs(ball) - 1;
            ball &= ball - 1;
            int cs = __shfl_sync(FULLM, cid, src);
            process_u4c(v, src, cs * 32 + (src & 3) * 8, Tcap, lv, li, T, lane);
        }
    }

    // ---- exact fp32 rescoring of the KEEP candidates ----
    float4 x[4];
    const float4* Xr = (const float4*)&E[(size_t)row * DIM];
    #pragma unroll
    for (int q = 0; q < 4; q++) x[q] = Xr[q * 32 + lane];
    const float ni = g_norms[row];

    float exd = INF;
    #pragma unroll 4
    for (int c = 0; c < KEEP; c++) {
        int idx = __shfl_sync(FULLM, li, c);
        const float4* Y = (const float4*)&E[(size_t)idx * DIM];
        float s = 0.f;
        #pragma unroll
        for (int q = 0; q < 4; q++) {
            float4 y = Y[q * 32 + lane];
            s = fmaf(x[q].x, y.x, fmaf(x[q].y, y.y, fmaf(x[q].z, y.z, fmaf(x[q].w, y.w, s))));
        }
        #pragma unroll
        for (int o = 16; o; o >>= 1) s += __shfl_xor_sync(FULLM, s, o);
        if (lane == c) exd = fmaxf(ni + g_norms[idx] - 2.f * s, 0.f);
    }

    // ---- warp bitonic sort of (exd, li) pairs ascending across 32 lanes ----
    float cur = exd; int cli = li;   // lanes >= KEEP hold INF
    #pragma unroll
    for (int k = 2; k <= 32; k <<= 1) {
        #pragma unroll
        for (int j = k >> 1; j; j >>= 1) {
            float ov = __shfl_xor_sync(FULLM, cur, j);
            int   oi = __shfl_xor_sync(FULLM, cli, j);
            bool lowerLane = !(lane & j);
            bool asc = !(lane & k);
            bool wantMin = (lowerLane == asc);
            bool take = wantMin ? (ov < cur) : (ov > cur);
            if (take) { cur = ov; cli = oi; }
        }
    }
    // lane s now holds the s-th smallest exact distance + its index
    float myd = cur; int myi = cli;

    // ---- curvature loss (exact, sorted ascending on lanes 0..14) ----
    float dd = (lane < KNN) ? sqrtf(fmaxf(myd, 1e-12f)) : 0.f;
    float ssum = dd;
    #pragma unroll
    for (int o = 16; o; o >>= 1) ssum += __shfl_xor_sync(FULLM, ssum, o);
    float mean = ssum / (float)KNN + 1e-8f;    // EPS_MEAN
    float df = 0.f;
    if (lane < KNN) {
        df = dd / mean - ref_curv[row * KNN + lane];
        g_knni[row * KNN + lane] = myi;
    }
    float l = df * df;
    #pragma unroll
    for (int o = 16; o; o >>= 1) l += __shfl_xor_sync(FULLM, l, o);
    if (lane == 0) atomicAdd(&g_acc[0], (double)l);
}

// ================= kernel 4: angular signature loss (proven version) ============
__global__ __launch_bounds__(256)
void angular_kernel(const float* __restrict__ E, const float* __restrict__ ref_ang) {
    const int row  = blockIdx.x;
    const int tid  = threadIdx.x;
    const int lane = tid & 31;
    const int w    = tid >> 5;

    __shared__ float ei[DIM];
    __shared__ float vh[KNN][DIM];
    __shared__ float nrm[KNN];
    __shared__ float cosv[128];
    __shared__ float lsum[8];

    if (tid < 128) {
        float4 q = *(const float4*)&E[(size_t)row * DIM + tid * 4];
        *(float4*)&ei[tid * 4] = q;
    }
    if (tid >= 105 && tid < 128) cosv[tid] = __int_as_float(0x7f800000);
    __syncthreads();

    for (int j = w; j < KNN; j += 8) {
        int nb = g_knni[row * KNN + j];
        const float4* src = (const float4*)&E[(size_t)nb * DIM];
        float s = 0.f;
        for (int c4 = lane; c4 < DIM / 4; c4 += 32) {
            float4 q = src[c4];
            float4 e = *(const float4*)&ei[c4 * 4];
            float4 v; v.x = q.x - e.x; v.y = q.y - e.y; v.z = q.z - e.z; v.w = q.w - e.w;
            *(float4*)&vh[j][c4 * 4] = v;
            s = fmaf(v.x, v.x, fmaf(v.y, v.y, fmaf(v.z, v.z, fmaf(v.w, v.w, s))));
        }
        #pragma unroll
        for (int o = 16; o; o >>= 1) s += __shfl_xor_sync(FULLM, s, o);
        if (!lane) nrm[j] = fmaxf(sqrtf(s), 1e-8f);   // EPS_NORM
    }
    __syncthreads();

    for (int p = w; p < NPAIR; p += 8) {
        int jj = 0, rem = p;
        while (rem >= (KNN - 1) - jj) { rem -= (KNN - 1) - jj; jj++; }
        int kk = jj + 1 + rem;
        float s = 0.f;
        for (int c = lane; c < DIM; c += 32)
            s = fmaf(vh[jj][c], vh[kk][c], s);
        #pragma unroll
        for (int o = 16; o; o >>= 1) s += __shfl_xor_sync(FULLM, s, o);
        if (!lane) cosv[p] = s / (nrm[jj] * nrm[kk]);
    }
    __syncthreads();

    for (int k = 2; k <= 128; k <<= 1) {
        for (int j2 = k >> 1; j2 > 0; j2 >>= 1) {
            if (tid < 128) {
                int ixj = tid ^ j2;
                if (ixj > tid) {
                    float a = cosv[tid], b = cosv[ixj];
                    bool up = ((tid & k) == 0);
                    if ((a > b) == up) { cosv[tid] = b; cosv[ixj] = a; }
                }
            }
            __syncthreads();
        }
    }

    float s = 0.f;
    for (int t2 = tid; t2 < NPAIR; t2 += 256) {
        float df = cosv[t2] - ref_ang[(size_t)row * NPAIR + t2];
        s = fmaf(df, df, s);
    }
    #pragma unroll
    for (int o = 16; o; o >>= 1) s += __shfl_xor_sync(FULLM, s, o);
    if (!lane) lsum[w] = s;
    __syncthreads();
    if (tid == 0) {
        float t2 = 0.f;
        #pragma unroll
        for (int q = 0; q < 8; q++) t2 += lsum[q];
        atomicAdd(&g_acc[1], (double)t2);
    }
}

// ================= kernel 5: finalize =================
__global__ void finalize_kernel(float* out) {
    double curv = g_acc[0] / ((double)NPTS * KNN);
    double ang  = g_acc[1] / ((double)NPTS * NPAIR);
    out[0] = (float)(0.3 * curv + 0.7 * ang);
}

// ================= launch =================
extern "C" void kernel_launch(void* const* d_in, const int* in_sizes, int n_in,
                              void* d_out, int out_size) {
    const float* emb      = (const float*)d_in[0];
    const float* ref_curv = (const float*)d_in[1];
    const float* ref_ang  = (const float*)d_in[2];
    float* out = (float*)d_out;

    cudaFuncSetAttribute(gemm_bf16_kernel,
                         cudaFuncAttributeMaxDynamicSharedMemorySize, SMEM_GEMM);

    const int NTILES = 1056;   // sum over r of (floor(r/2)+1), r in 0..63

    prep_kernel<<<NPTS / 8, 256>>>(emb);
    gemm_bf16_kernel<<<NTILES, 256, SMEM_GEMM>>>();
    topk_curv_kernel<<<NPTS / 8, 256>>>(emb, ref_curv);
    angular_kernel<<<NPTS, 256>>>(emb, ref_ang);
    finalize_kernel<<<1, 1>>>(out);
}